// round 13
// baseline (speedup 1.0000x reference)
#include <cuda_runtime.h>
#include <cstdint>

#define NMAX 50000
#define EMAX 1600000
#define HC   64
#define NEG_SLOPE 0.2f

// ---------------- device scratch (no allocation allowed) ----------------
__device__ float g_xl [NMAX * HC];
__device__ float g_xr [NMAX * HC];
__device__ float g_h  [NMAX * HC];
__device__ int   g_deg[NMAX];
__device__ int   g_off[NMAX + 1];
__device__ int   g_pos[NMAX];
__device__ int   g_csr_src[EMAX];
__device__ int   g_is64;

__device__ __forceinline__ float lrelu(float v) {
    return v > 0.f ? v : NEG_SLOPE * v;
}

__device__ __forceinline__ uint32_t tf32_round(float x) {
    uint32_t r;
    asm("cvt.rna.tf32.f32 %0, %1;" : "=r"(r) : "f"(x));
    return r;
}

// ---------------- edge_index dtype detection ------------------------------
__global__ void detect_dtype_kernel(const int* __restrict__ w) {
    if (threadIdx.x == 0 && blockIdx.x == 0) {
        int any = 0;
        for (int i = 0; i < 64; i++) any |= w[2 * i + 1];
        g_is64 = (any == 0) ? 1 : 0;
    }
}
__device__ __forceinline__ int load_idx(const void* ei, int i) {
    return g_is64 ? (int)((const long long*)ei)[i] : ((const int*)ei)[i];
}

// ---------------- CSR build (4 edges/thread) ------------------------------
__global__ void hist_kernel(const void* __restrict__ ei, int E) {
    int base = (blockIdx.x * blockDim.x + threadIdx.x) * 4;
    if (base >= E) return;
    int n = E - base; if (n > 4) n = 4;
    int d[4];
#pragma unroll
    for (int j = 0; j < 4; j++)
        if (j < n) d[j] = load_idx(ei, base + j + E);
#pragma unroll
    for (int j = 0; j < 4; j++)
        if (j < n) atomicAdd(&g_deg[d[j]], 1);
}

__global__ void __launch_bounds__(1024) scan_kernel(int N) {
    __shared__ int part[1024];
    int t = threadIdx.x;
    int chunk = (N + 1023) >> 10;
    int b = t * chunk; if (b > N) b = N;
    int e = b + chunk; if (e > N) e = N;
    int s = 0;
    for (int i = b; i < e; i++) s += g_deg[i];
    part[t] = s;
    __syncthreads();
    for (int d = 1; d < 1024; d <<= 1) {
        int v = (t >= d) ? part[t - d] : 0;
        __syncthreads();
        part[t] += v;
        __syncthreads();
    }
    int run = (t == 0) ? 0 : part[t - 1];
    for (int i = b; i < e; i++) {
        g_off[i] = run;
        g_pos[i] = run;
        run += g_deg[i];
    }
    if (e == N) g_off[N] = run;
}

__global__ void scatter_kernel(const void* __restrict__ ei, int E) {
    int base = (blockIdx.x * blockDim.x + threadIdx.x) * 4;
    if (base >= E) return;
    int n = E - base; if (n > 4) n = 4;
    int s[4], d[4];
#pragma unroll
    for (int j = 0; j < 4; j++)
        if (j < n) { s[j] = load_idx(ei, base + j); d[j] = load_idx(ei, base + j + E); }
    int slot[4];
#pragma unroll
    for (int j = 0; j < 4; j++)
        if (j < n) slot[j] = atomicAdd(&g_pos[d[j]], 1);
#pragma unroll
    for (int j = 0; j < 4; j++)
        if (j < n) g_csr_src[slot[j]] = s[j];
}

// ---------------- split-tf32 mma.sync GEMM (R12, unchanged) ---------------
#define ASTRIDE 36
#define BSTRIDE 72
#define SM_FLOATS (2 * 128 * ASTRIDE + 2 * 32 * BSTRIDE)   // 13824
#define SM_BYTES  (SM_FLOATS * 4)                          // 55296

__device__ __forceinline__ void mma8(float* c, const uint32_t* a, const uint32_t* b) {
    asm volatile(
        "mma.sync.aligned.m16n8k8.row.col.f32.tf32.tf32.f32 "
        "{%0,%1,%2,%3}, {%4,%5,%6,%7}, {%8,%9}, {%0,%1,%2,%3};"
        : "+f"(c[0]), "+f"(c[1]), "+f"(c[2]), "+f"(c[3])
        : "r"(a[0]), "r"(a[1]), "r"(a[2]), "r"(a[3]), "r"(b[0]), "r"(b[1]));
}

template<int ACT>  // 0 = none, 1 = sigmoid
__global__ void __launch_bounds__(256, 2) mma_gemm_kernel(
    const float* __restrict__ A,
    const float* __restrict__ W0, const float* __restrict__ b0, float* __restrict__ C0,
    const float* __restrict__ W1, const float* __restrict__ b1, float* __restrict__ C1,
    int M, int K, int NC)
{
    const float* W    = blockIdx.z ? W1 : W0;
    const float* bias = blockIdx.z ? b1 : b0;
    float*       C    = blockIdx.z ? C1 : C0;

    extern __shared__ float sm[];
    float* Ahi = sm;
    float* Alo = sm + 128 * ASTRIDE;
    float* Bhi = sm + 2 * 128 * ASTRIDE;
    float* Blo = Bhi + 32 * BSTRIDE;

    const int tid = threadIdx.x;
    const int wid = tid >> 5;
    const int lid = tid & 31;
    const int t   = lid & 3;
    const int g   = lid >> 2;
    const int wm  = wid & 3;
    const int wn  = wid >> 2;
    const int bm  = blockIdx.x * 128;
    const int bn  = blockIdx.y * 64;

    const int a_row = tid >> 3;
    const int a_c4  = (tid & 7) * 4;
    const int b_kr  = tid >> 4;
    const int b_cw  = (tid & 15) * 4;

    float acc[2][4][4];
#pragma unroll
    for (int i = 0; i < 2; i++)
#pragma unroll
        for (int j = 0; j < 4; j++)
#pragma unroll
            for (int q = 0; q < 4; q++) acc[i][j][q] = 0.f;

    float4 pa[4], pb[2];
#pragma unroll
    for (int it = 0; it < 4; it++) {
        int row = a_row + it * 32;
        pa[it] = make_float4(0.f, 0.f, 0.f, 0.f);
        if (bm + row < M)
            pa[it] = *(const float4*)(A + (size_t)(bm + row) * K + a_c4);
    }
#pragma unroll
    for (int it = 0; it < 2; it++) {
        int kr = b_kr + it * 16;
        pb[it] = *(const float4*)(W + (size_t)kr * NC + bn + b_cw);
    }

    for (int kk = 0; kk < K; kk += 32) {
#pragma unroll
        for (int it = 0; it < 4; it++) {
            int row = a_row + it * 32;
            float4 v = pa[it];
            float4 hf = make_float4(
                __uint_as_float(tf32_round(v.x)), __uint_as_float(tf32_round(v.y)),
                __uint_as_float(tf32_round(v.z)), __uint_as_float(tf32_round(v.w)));
            float4 lf = make_float4(
                __uint_as_float(tf32_round(v.x - hf.x)),
                __uint_as_float(tf32_round(v.y - hf.y)),
                __uint_as_float(tf32_round(v.z - hf.z)),
                __uint_as_float(tf32_round(v.w - hf.w)));
            *(float4*)(Ahi + row * ASTRIDE + a_c4) = hf;
            *(float4*)(Alo + row * ASTRIDE + a_c4) = lf;
        }
#pragma unroll
        for (int it = 0; it < 2; it++) {
            int kr = b_kr + it * 16;
            float4 v = pb[it];
            float4 hf = make_float4(
                __uint_as_float(tf32_round(v.x)), __uint_as_float(tf32_round(v.y)),
                __uint_as_float(tf32_round(v.z)), __uint_as_float(tf32_round(v.w)));
            float4 lf = make_float4(
                __uint_as_float(tf32_round(v.x - hf.x)),
                __uint_as_float(tf32_round(v.y - hf.y)),
                __uint_as_float(tf32_round(v.z - hf.z)),
                __uint_as_float(tf32_round(v.w - hf.w)));
            *(float4*)(Bhi + kr * BSTRIDE + b_cw) = hf;
            *(float4*)(Blo + kr * BSTRIDE + b_cw) = lf;
        }
        __syncthreads();

        if (kk + 32 < K) {
#pragma unroll
            for (int it = 0; it < 4; it++) {
                int row = a_row + it * 32;
                pa[it] = make_float4(0.f, 0.f, 0.f, 0.f);
                if (bm + row < M)
                    pa[it] = *(const float4*)(A + (size_t)(bm + row) * K + kk + 32 + a_c4);
            }
#pragma unroll
            for (int it = 0; it < 2; it++) {
                int kr = b_kr + it * 16;
                pb[it] = *(const float4*)(W + (size_t)(kk + 32 + kr) * NC + bn + b_cw);
            }
        }

#pragma unroll
        for (int q = 0; q < 4; q++) {
            const int kq = q * 8;
            uint32_t ahi[2][4], alo[2][4];
#pragma unroll
            for (int i = 0; i < 2; i++) {
                int mb = wm * 32 + i * 16;
                const uint32_t* ph = (const uint32_t*)Ahi;
                const uint32_t* pl = (const uint32_t*)Alo;
                int o00 = (mb + g)     * ASTRIDE + kq + t;
                int o10 = (mb + g + 8) * ASTRIDE + kq + t;
                ahi[i][0] = ph[o00];     ahi[i][1] = ph[o10];
                ahi[i][2] = ph[o00 + 4]; ahi[i][3] = ph[o10 + 4];
                alo[i][0] = pl[o00];     alo[i][1] = pl[o10];
                alo[i][2] = pl[o00 + 4]; alo[i][3] = pl[o10 + 4];
            }
            uint32_t bh[4][2], bl[4][2];
#pragma unroll
            for (int j = 0; j < 4; j++) {
                int nb = wn * 32 + j * 8;
                const uint32_t* ph = (const uint32_t*)Bhi;
                const uint32_t* pl = (const uint32_t*)Blo;
                int o0 = (kq + t)     * BSTRIDE + nb + g;
                int o1 = (kq + t + 4) * BSTRIDE + nb + g;
                bh[j][0] = ph[o0]; bh[j][1] = ph[o1];
                bl[j][0] = pl[o0]; bl[j][1] = pl[o1];
            }
#pragma unroll
            for (int i = 0; i < 2; i++)
#pragma unroll
                for (int j = 0; j < 4; j++) {
                    mma8(acc[i][j], ahi[i], bh[j]);
                    mma8(acc[i][j], ahi[i], bl[j]);
                    mma8(acc[i][j], alo[i], bh[j]);
                }
        }
        __syncthreads();
    }

#pragma unroll
    for (int i = 0; i < 2; i++) {
        int r0 = bm + wm * 32 + i * 16 + g;
#pragma unroll
        for (int j = 0; j < 4; j++) {
            int col = bn + wn * 32 + j * 8 + 2 * t;
            float bz0 = bias[col], bz1 = bias[col + 1];
            float v0 = acc[i][j][0] + bz0;
            float v1 = acc[i][j][1] + bz1;
            float v2 = acc[i][j][2] + bz0;
            float v3 = acc[i][j][3] + bz1;
            if (ACT == 1) {
                v0 = 1.f / (1.f + __expf(-v0));
                v1 = 1.f / (1.f + __expf(-v1));
                v2 = 1.f / (1.f + __expf(-v2));
                v3 = 1.f / (1.f + __expf(-v3));
            }
            if (r0 < M)
                *(float2*)(C + (size_t)r0 * NC + col) = make_float2(v0, v1);
            if (r0 + 8 < M)
                *(float2*)(C + (size_t)(r0 + 8) * NC + col) = make_float2(v2, v3);
        }
    }
}

// ---------------- fused per-node GATv2 aggregation ------------------------
__device__ __forceinline__ void gat_edge_step(
    float2 xv, float2 xrv, float a0, float a1,
    float& accx, float& accy, float& den)
{
    float p = a0 * lrelu(xv.x + xrv.x) + a1 * lrelu(xv.y + xrv.y);
    p += __shfl_xor_sync(0xffffffffu, p, 1);
    p += __shfl_xor_sync(0xffffffffu, p, 2);
    p += __shfl_xor_sync(0xffffffffu, p, 4);
    float ex = __expf(p);
    den  += ex;
    accx += ex * xv.x;
    accy += ex * xv.y;
}

__global__ void __launch_bounds__(256) gat_aggregate_kernel(
    const float* __restrict__ xl, const float* __restrict__ xr,
    const float* __restrict__ att, const float* __restrict__ bias,
    float* __restrict__ out, int N)
{
    int warp = (blockIdx.x * blockDim.x + threadIdx.x) >> 5;
    int c    = threadIdx.x & 31;
    if (warp >= N) return;
    const int d = warp;

    const float a0 = att[2 * c];
    const float a1 = att[2 * c + 1];
    const float2 xrv = *(const float2*)(xr + (size_t)d * 64 + 2 * c);

    const int beg = g_off[d];
    const int end = g_off[d + 1];

    float accx = 0.f, accy = 0.f, den = 0.f;

    for (int i = beg; i < end; ) {
        int cnt = end - i;
        if (cnt > 32) cnt = 32;
        int my_src = (c < cnt) ? g_csr_src[i + c] : 0;

        int j = 0;
        for (; j + 8 <= cnt; j += 8) {
            float2 v[8];
#pragma unroll
            for (int u = 0; u < 8; u++) {
                int s = __shfl_sync(0xffffffffu, my_src, j + u);
                v[u] = *(const float2*)(xl + (size_t)s * 64 + 2 * c);
            }
#pragma unroll
            for (int u = 0; u < 8; u++)
                gat_edge_step(v[u], xrv, a0, a1, accx, accy, den);
        }
        for (; j + 4 <= cnt; j += 4) {
            float2 v[4];
#pragma unroll
            for (int u = 0; u < 4; u++) {
                int s = __shfl_sync(0xffffffffu, my_src, j + u);
                v[u] = *(const float2*)(xl + (size_t)s * 64 + 2 * c);
            }
#pragma unroll
            for (int u = 0; u < 4; u++)
                gat_edge_step(v[u], xrv, a0, a1, accx, accy, den);
        }
        for (; j < cnt; j++) {
            int s = __shfl_sync(0xffffffffu, my_src, j);
            float2 v = *(const float2*)(xl + (size_t)s * 64 + 2 * c);
            gat_edge_step(v, xrv, a0, a1, accx, accy, den);
        }
        i += cnt;
    }

    float inv = (den > 0.f) ? (1.f / den) : 0.f;
    float ox = fmaxf(accx * inv + bias[2 * c],     0.f);
    float oy = fmaxf(accy * inv + bias[2 * c + 1], 0.f);
    *(float2*)(out + (size_t)d * 64 + 2 * c) = make_float2(ox, oy);
}

// ---------------- launch --------------------------------------------------
// DIAGNOSTIC ROUND: every GEMM launch is issued TWICE (idempotent, identical
// outputs). dur_us delta vs the 370.2us baseline == total GEMM phase time.
extern "C" void kernel_launch(void* const* d_in, const int* in_sizes, int n_in,
                              void* d_out, int out_size)
{
    const float* x    = (const float*)d_in[0];
    const void*  ei   = d_in[1];
    const float* Wl1  = (const float*)d_in[2];
    const float* bl1  = (const float*)d_in[3];
    const float* Wr1  = (const float*)d_in[4];
    const float* br1  = (const float*)d_in[5];
    const float* att1 = (const float*)d_in[6];
    const float* bias1= (const float*)d_in[7];
    const float* Wl2  = (const float*)d_in[8];
    const float* bl2  = (const float*)d_in[9];
    const float* Wr2  = (const float*)d_in[10];
    const float* br2  = (const float*)d_in[11];
    const float* att2 = (const float*)d_in[12];
    const float* bias2= (const float*)d_in[13];
    const float* Wo   = (const float*)d_in[14];
    const float* bo   = (const float*)d_in[15];

    const int Nn = in_sizes[0] / 256;      // 50000
    const int E  = in_sizes[1] / 2;        // 1600000

    float *p_xl, *p_xr, *p_h;
    int *p_deg;
    cudaGetSymbolAddress((void**)&p_xl,  g_xl);
    cudaGetSymbolAddress((void**)&p_xr,  g_xr);
    cudaGetSymbolAddress((void**)&p_h,   g_h);
    cudaGetSymbolAddress((void**)&p_deg, g_deg);

    static cudaStream_t s_csr = nullptr;
    static cudaEvent_t  ev_fork = nullptr, ev_join = nullptr;
    if (s_csr == nullptr) {
        cudaStreamCreateWithFlags(&s_csr, cudaStreamNonBlocking);
        cudaEventCreateWithFlags(&ev_fork, cudaEventDisableTiming);
        cudaEventCreateWithFlags(&ev_join, cudaEventDisableTiming);
        cudaFuncSetAttribute(mma_gemm_kernel<0>,
                             cudaFuncAttributeMaxDynamicSharedMemorySize, SM_BYTES);
        cudaFuncSetAttribute(mma_gemm_kernel<1>,
                             cudaFuncAttributeMaxDynamicSharedMemorySize, SM_BYTES);
    }

    const int gm = (Nn + 127) / 128;       // 391
    const int eb4 = (E / 4 + 255) / 256;
    const int agb = (Nn * 32 + 255) / 256;

    // ---- fork: CSR build on side stream, concurrent with layer-1 GEMM ----
    cudaEventRecord(ev_fork, 0);
    cudaStreamWaitEvent(s_csr, ev_fork, 0);

    detect_dtype_kernel<<<1, 32, 0, s_csr>>>((const int*)ei);
    cudaMemsetAsync(p_deg, 0, (size_t)Nn * sizeof(int), s_csr);
    hist_kernel<<<eb4, 256, 0, s_csr>>>(ei, E);
    scan_kernel<<<1, 1024, 0, s_csr>>>(Nn);
    scatter_kernel<<<eb4, 256, 0, s_csr>>>(ei, E);
    cudaEventRecord(ev_join, s_csr);

    // ---- layer 1 GEMMs (x2 for timing) ----
    mma_gemm_kernel<0><<<dim3(gm, 1, 2), 256, SM_BYTES>>>(
        x, Wl1, bl1, p_xl, Wr1, br1, p_xr, Nn, 256, 64);
    mma_gemm_kernel<0><<<dim3(gm, 1, 2), 256, SM_BYTES>>>(
        x, Wl1, bl1, p_xl, Wr1, br1, p_xr, Nn, 256, 64);

    cudaStreamWaitEvent(0, ev_join, 0);
    gat_aggregate_kernel<<<agb, 256>>>(p_xl, p_xr, att1, bias1, p_h, Nn);

    // ---- layer 2 (x2 for timing) ----
    mma_gemm_kernel<0><<<dim3(gm, 1, 2), 256, SM_BYTES>>>(
        p_h, Wl2, bl2, p_xl, Wr2, br2, p_xr, Nn, 64, 64);
    mma_gemm_kernel<0><<<dim3(gm, 1, 2), 256, SM_BYTES>>>(
        p_h, Wl2, bl2, p_xl, Wr2, br2, p_xr, Nn, 64, 64);
    gat_aggregate_kernel<<<agb, 256>>>(p_xl, p_xr, att2, bias2, p_h, Nn);

    // ---- output head (x2 for timing) ----
    mma_gemm_kernel<1><<<dim3(gm, 4, 1), 256, SM_BYTES>>>(
        p_h, Wo, bo, (float*)d_out, Wo, bo, (float*)d_out, Nn, 64, 256);
    mma_gemm_kernel<1><<<dim3(gm, 4, 1), 256, SM_BYTES>>>(
        p_h, Wo, bo, (float*)d_out, Wo, bo, (float*)d_out, Nn, 64, 256);
}

// round 14
// speedup vs baseline: 1.2645x; 1.2645x over previous
#include <cuda_runtime.h>
#include <cstdint>

#define NMAX 50000
#define EMAX 1600000
#define HC   64
#define NEG_SLOPE 0.2f

// ---------------- device scratch (no allocation allowed) ----------------
__device__ float g_xl [NMAX * HC];
__device__ float g_xr [NMAX * HC];
__device__ float g_h  [NMAX * HC];
__device__ int   g_deg[NMAX];
__device__ int   g_off[NMAX + 1];
__device__ int   g_pos[NMAX];
__device__ int   g_csr_src[EMAX];
__device__ int   g_is64;

__device__ __forceinline__ float lrelu(float v) {
    return v > 0.f ? v : NEG_SLOPE * v;
}

__device__ __forceinline__ uint32_t tf32_round(float x) {
    uint32_t r;
    asm("cvt.rna.tf32.f32 %0, %1;" : "=r"(r) : "f"(x));
    return r;
}

// ---------------- edge_index dtype detection ------------------------------
__global__ void detect_dtype_kernel(const int* __restrict__ w) {
    if (threadIdx.x == 0 && blockIdx.x == 0) {
        int any = 0;
        for (int i = 0; i < 64; i++) any |= w[2 * i + 1];
        g_is64 = (any == 0) ? 1 : 0;
    }
}
__device__ __forceinline__ int load_idx(const void* ei, int i) {
    return g_is64 ? (int)((const long long*)ei)[i] : ((const int*)ei)[i];
}

// ---------------- CSR build (4 edges/thread) ------------------------------
__global__ void hist_kernel(const void* __restrict__ ei, int E) {
    int base = (blockIdx.x * blockDim.x + threadIdx.x) * 4;
    if (base >= E) return;
    int n = E - base; if (n > 4) n = 4;
    int d[4];
#pragma unroll
    for (int j = 0; j < 4; j++)
        if (j < n) d[j] = load_idx(ei, base + j + E);
#pragma unroll
    for (int j = 0; j < 4; j++)
        if (j < n) atomicAdd(&g_deg[d[j]], 1);
}

__global__ void __launch_bounds__(1024) scan_kernel(int N) {
    __shared__ int part[1024];
    int t = threadIdx.x;
    int chunk = (N + 1023) >> 10;
    int b = t * chunk; if (b > N) b = N;
    int e = b + chunk; if (e > N) e = N;
    int s = 0;
    for (int i = b; i < e; i++) s += g_deg[i];
    part[t] = s;
    __syncthreads();
    for (int d = 1; d < 1024; d <<= 1) {
        int v = (t >= d) ? part[t - d] : 0;
        __syncthreads();
        part[t] += v;
        __syncthreads();
    }
    int run = (t == 0) ? 0 : part[t - 1];
    for (int i = b; i < e; i++) {
        g_off[i] = run;
        g_pos[i] = run;
        run += g_deg[i];
    }
    if (e == N) g_off[N] = run;
}

__global__ void scatter_kernel(const void* __restrict__ ei, int E) {
    int base = (blockIdx.x * blockDim.x + threadIdx.x) * 4;
    if (base >= E) return;
    int n = E - base; if (n > 4) n = 4;
    int s[4], d[4];
#pragma unroll
    for (int j = 0; j < 4; j++)
        if (j < n) { s[j] = load_idx(ei, base + j); d[j] = load_idx(ei, base + j + E); }
    int slot[4];
#pragma unroll
    for (int j = 0; j < 4; j++)
        if (j < n) slot[j] = atomicAdd(&g_pos[d[j]], 1);
#pragma unroll
    for (int j = 0; j < 4; j++)
        if (j < n) g_csr_src[slot[j]] = s[j];
}

// ---------------- split-tf32 mma.sync GEMM (R12, unchanged) ---------------
#define ASTRIDE 36
#define BSTRIDE 72
#define SM_FLOATS (2 * 128 * ASTRIDE + 2 * 32 * BSTRIDE)   // 13824
#define SM_BYTES  (SM_FLOATS * 4)                          // 55296

__device__ __forceinline__ void mma8(float* c, const uint32_t* a, const uint32_t* b) {
    asm volatile(
        "mma.sync.aligned.m16n8k8.row.col.f32.tf32.tf32.f32 "
        "{%0,%1,%2,%3}, {%4,%5,%6,%7}, {%8,%9}, {%0,%1,%2,%3};"
        : "+f"(c[0]), "+f"(c[1]), "+f"(c[2]), "+f"(c[3])
        : "r"(a[0]), "r"(a[1]), "r"(a[2]), "r"(a[3]), "r"(b[0]), "r"(b[1]));
}

template<int ACT>  // 0 = none, 1 = sigmoid
__global__ void __launch_bounds__(256, 2) mma_gemm_kernel(
    const float* __restrict__ A,
    const float* __restrict__ W0, const float* __restrict__ b0, float* __restrict__ C0,
    const float* __restrict__ W1, const float* __restrict__ b1, float* __restrict__ C1,
    int M, int K, int NC)
{
    const float* W    = blockIdx.z ? W1 : W0;
    const float* bias = blockIdx.z ? b1 : b0;
    float*       C    = blockIdx.z ? C1 : C0;

    extern __shared__ float sm[];
    float* Ahi = sm;
    float* Alo = sm + 128 * ASTRIDE;
    float* Bhi = sm + 2 * 128 * ASTRIDE;
    float* Blo = Bhi + 32 * BSTRIDE;

    const int tid = threadIdx.x;
    const int wid = tid >> 5;
    const int lid = tid & 31;
    const int t   = lid & 3;
    const int g   = lid >> 2;
    const int wm  = wid & 3;
    const int wn  = wid >> 2;
    const int bm  = blockIdx.x * 128;
    const int bn  = blockIdx.y * 64;

    const int a_row = tid >> 3;
    const int a_c4  = (tid & 7) * 4;
    const int b_kr  = tid >> 4;
    const int b_cw  = (tid & 15) * 4;

    float acc[2][4][4];
#pragma unroll
    for (int i = 0; i < 2; i++)
#pragma unroll
        for (int j = 0; j < 4; j++)
#pragma unroll
            for (int q = 0; q < 4; q++) acc[i][j][q] = 0.f;

    float4 pa[4], pb[2];
#pragma unroll
    for (int it = 0; it < 4; it++) {
        int row = a_row + it * 32;
        pa[it] = make_float4(0.f, 0.f, 0.f, 0.f);
        if (bm + row < M)
            pa[it] = *(const float4*)(A + (size_t)(bm + row) * K + a_c4);
    }
#pragma unroll
    for (int it = 0; it < 2; it++) {
        int kr = b_kr + it * 16;
        pb[it] = *(const float4*)(W + (size_t)kr * NC + bn + b_cw);
    }

    for (int kk = 0; kk < K; kk += 32) {
#pragma unroll
        for (int it = 0; it < 4; it++) {
            int row = a_row + it * 32;
            float4 v = pa[it];
            float4 hf = make_float4(
                __uint_as_float(tf32_round(v.x)), __uint_as_float(tf32_round(v.y)),
                __uint_as_float(tf32_round(v.z)), __uint_as_float(tf32_round(v.w)));
            float4 lf = make_float4(
                __uint_as_float(tf32_round(v.x - hf.x)),
                __uint_as_float(tf32_round(v.y - hf.y)),
                __uint_as_float(tf32_round(v.z - hf.z)),
                __uint_as_float(tf32_round(v.w - hf.w)));
            *(float4*)(Ahi + row * ASTRIDE + a_c4) = hf;
            *(float4*)(Alo + row * ASTRIDE + a_c4) = lf;
        }
#pragma unroll
        for (int it = 0; it < 2; it++) {
            int kr = b_kr + it * 16;
            float4 v = pb[it];
            float4 hf = make_float4(
                __uint_as_float(tf32_round(v.x)), __uint_as_float(tf32_round(v.y)),
                __uint_as_float(tf32_round(v.z)), __uint_as_float(tf32_round(v.w)));
            float4 lf = make_float4(
                __uint_as_float(tf32_round(v.x - hf.x)),
                __uint_as_float(tf32_round(v.y - hf.y)),
                __uint_as_float(tf32_round(v.z - hf.z)),
                __uint_as_float(tf32_round(v.w - hf.w)));
            *(float4*)(Bhi + kr * BSTRIDE + b_cw) = hf;
            *(float4*)(Blo + kr * BSTRIDE + b_cw) = lf;
        }
        __syncthreads();

        if (kk + 32 < K) {
#pragma unroll
            for (int it = 0; it < 4; it++) {
                int row = a_row + it * 32;
                pa[it] = make_float4(0.f, 0.f, 0.f, 0.f);
                if (bm + row < M)
                    pa[it] = *(const float4*)(A + (size_t)(bm + row) * K + kk + 32 + a_c4);
            }
#pragma unroll
            for (int it = 0; it < 2; it++) {
                int kr = b_kr + it * 16;
                pb[it] = *(const float4*)(W + (size_t)(kk + 32 + kr) * NC + bn + b_cw);
            }
        }

#pragma unroll
        for (int q = 0; q < 4; q++) {
            const int kq = q * 8;
            uint32_t ahi[2][4], alo[2][4];
#pragma unroll
            for (int i = 0; i < 2; i++) {
                int mb = wm * 32 + i * 16;
                const uint32_t* ph = (const uint32_t*)Ahi;
                const uint32_t* pl = (const uint32_t*)Alo;
                int o00 = (mb + g)     * ASTRIDE + kq + t;
                int o10 = (mb + g + 8) * ASTRIDE + kq + t;
                ahi[i][0] = ph[o00];     ahi[i][1] = ph[o10];
                ahi[i][2] = ph[o00 + 4]; ahi[i][3] = ph[o10 + 4];
                alo[i][0] = pl[o00];     alo[i][1] = pl[o10];
                alo[i][2] = pl[o00 + 4]; alo[i][3] = pl[o10 + 4];
            }
            uint32_t bh[4][2], bl[4][2];
#pragma unroll
            for (int j = 0; j < 4; j++) {
                int nb = wn * 32 + j * 8;
                const uint32_t* ph = (const uint32_t*)Bhi;
                const uint32_t* pl = (const uint32_t*)Blo;
                int o0 = (kq + t)     * BSTRIDE + nb + g;
                int o1 = (kq + t + 4) * BSTRIDE + nb + g;
                bh[j][0] = ph[o0]; bh[j][1] = ph[o1];
                bl[j][0] = pl[o0]; bl[j][1] = pl[o1];
            }
#pragma unroll
            for (int i = 0; i < 2; i++)
#pragma unroll
                for (int j = 0; j < 4; j++) {
                    mma8(acc[i][j], ahi[i], bh[j]);
                    mma8(acc[i][j], ahi[i], bl[j]);
                    mma8(acc[i][j], alo[i], bh[j]);
                }
        }
        __syncthreads();
    }

#pragma unroll
    for (int i = 0; i < 2; i++) {
        int r0 = bm + wm * 32 + i * 16 + g;
#pragma unroll
        for (int j = 0; j < 4; j++) {
            int col = bn + wn * 32 + j * 8 + 2 * t;
            float bz0 = bias[col], bz1 = bias[col + 1];
            float v0 = acc[i][j][0] + bz0;
            float v1 = acc[i][j][1] + bz1;
            float v2 = acc[i][j][2] + bz0;
            float v3 = acc[i][j][3] + bz1;
            if (ACT == 1) {
                v0 = 1.f / (1.f + __expf(-v0));
                v1 = 1.f / (1.f + __expf(-v1));
                v2 = 1.f / (1.f + __expf(-v2));
                v3 = 1.f / (1.f + __expf(-v3));
            }
            if (r0 < M)
                *(float2*)(C + (size_t)r0 * NC + col) = make_float2(v0, v1);
            if (r0 + 8 < M)
                *(float2*)(C + (size_t)(r0 + 8) * NC + col) = make_float2(v2, v3);
        }
    }
}

// ---------------- fused per-node GATv2 aggregation (2 edges/iter) ---------
// Warp per dst node. Lanes 0-15 handle edge j, lanes 16-31 edge j+1.
// q = lid&15 owns channels 4q..4q+3 (head = q>>2, 4 lanes per head).
// Per 2 edges: 1 idx-shfl + 1 LDG.128 + 2-shfl butterfly + 1 exp.
__global__ void __launch_bounds__(256) gat_aggregate_kernel(
    const float* __restrict__ xl, const float* __restrict__ xr,
    const float* __restrict__ att, const float* __restrict__ bias,
    float* __restrict__ out, int N)
{
    const int warp = (blockIdx.x * blockDim.x + threadIdx.x) >> 5;
    const int lid  = threadIdx.x & 31;
    if (warp >= N) return;
    const int d  = warp;
    const int eh = lid >> 4;      // edge half: 0 or 1
    const int q  = lid & 15;      // channel quad

    const float4 a4  = *(const float4*)(att + q * 4);
    const float4 xr4 = *(const float4*)(xr + (size_t)d * 64 + q * 4);

    const int beg = g_off[d];
    const int end = g_off[d + 1];

    float4 acc = make_float4(0.f, 0.f, 0.f, 0.f);
    float  den = 0.f;

    for (int i = beg; i < end; ) {
        int cnt = end - i;
        if (cnt > 32) cnt = 32;
        int my_src = (lid < cnt) ? g_csr_src[i + lid] : 0;

        int j = 0;
        // 8 edges per unrolled block (4 x 2-edge iters), loads batched
        for (; j + 8 <= cnt; j += 8) {
            int s[4];
            float4 v[4];
#pragma unroll
            for (int u = 0; u < 4; u++)
                s[u] = __shfl_sync(0xffffffffu, my_src, j + 2 * u + eh);
#pragma unroll
            for (int u = 0; u < 4; u++)
                v[u] = *(const float4*)(xl + (size_t)s[u] * 64 + q * 4);
#pragma unroll
            for (int u = 0; u < 4; u++) {
                float p = a4.x * lrelu(v[u].x + xr4.x)
                        + a4.y * lrelu(v[u].y + xr4.y)
                        + a4.z * lrelu(v[u].z + xr4.z)
                        + a4.w * lrelu(v[u].w + xr4.w);
                p += __shfl_xor_sync(0xffffffffu, p, 1);
                p += __shfl_xor_sync(0xffffffffu, p, 2);
                float ex = __expf(p);
                den   += ex;
                acc.x += ex * v[u].x;
                acc.y += ex * v[u].y;
                acc.z += ex * v[u].z;
                acc.w += ex * v[u].w;
            }
        }
        // remainder: 2 edges at a time, tail-guarded
        for (; j < cnt; j += 2) {
            int idx   = j + eh;
            bool val  = idx < cnt;
            int s     = __shfl_sync(0xffffffffu, my_src, val ? idx : 0);
            float4 v  = make_float4(0.f, 0.f, 0.f, 0.f);
            if (val) v = *(const float4*)(xl + (size_t)s * 64 + q * 4);
            float p = a4.x * lrelu(v.x + xr4.x)
                    + a4.y * lrelu(v.y + xr4.y)
                    + a4.z * lrelu(v.z + xr4.z)
                    + a4.w * lrelu(v.w + xr4.w);
            p += __shfl_xor_sync(0xffffffffu, p, 1);
            p += __shfl_xor_sync(0xffffffffu, p, 2);
            float ex = val ? __expf(p) : 0.f;
            den   += ex;
            acc.x += ex * v.x;
            acc.y += ex * v.y;
            acc.z += ex * v.z;
            acc.w += ex * v.w;
        }
        i += cnt;
    }

    // combine the two edge-halves (xor 16)
    acc.x += __shfl_xor_sync(0xffffffffu, acc.x, 16);
    acc.y += __shfl_xor_sync(0xffffffffu, acc.y, 16);
    acc.z += __shfl_xor_sync(0xffffffffu, acc.z, 16);
    acc.w += __shfl_xor_sync(0xffffffffu, acc.w, 16);
    den   += __shfl_xor_sync(0xffffffffu, den,   16);

    if (eh == 0) {
        float inv = (den > 0.f) ? (1.f / den) : 0.f;
        float4 b4 = *(const float4*)(bias + q * 4);
        float4 o;
        o.x = fmaxf(acc.x * inv + b4.x, 0.f);
        o.y = fmaxf(acc.y * inv + b4.y, 0.f);
        o.z = fmaxf(acc.z * inv + b4.z, 0.f);
        o.w = fmaxf(acc.w * inv + b4.w, 0.f);
        *(float4*)(out + (size_t)d * 64 + q * 4) = o;
    }
}

// ---------------- launch --------------------------------------------------
extern "C" void kernel_launch(void* const* d_in, const int* in_sizes, int n_in,
                              void* d_out, int out_size)
{
    const float* x    = (const float*)d_in[0];
    const void*  ei   = d_in[1];
    const float* Wl1  = (const float*)d_in[2];
    const float* bl1  = (const float*)d_in[3];
    const float* Wr1  = (const float*)d_in[4];
    const float* br1  = (const float*)d_in[5];
    const float* att1 = (const float*)d_in[6];
    const float* bias1= (const float*)d_in[7];
    const float* Wl2  = (const float*)d_in[8];
    const float* bl2  = (const float*)d_in[9];
    const float* Wr2  = (const float*)d_in[10];
    const float* br2  = (const float*)d_in[11];
    const float* att2 = (const float*)d_in[12];
    const float* bias2= (const float*)d_in[13];
    const float* Wo   = (const float*)d_in[14];
    const float* bo   = (const float*)d_in[15];

    const int Nn = in_sizes[0] / 256;      // 50000
    const int E  = in_sizes[1] / 2;        // 1600000

    float *p_xl, *p_xr, *p_h;
    int *p_deg;
    cudaGetSymbolAddress((void**)&p_xl,  g_xl);
    cudaGetSymbolAddress((void**)&p_xr,  g_xr);
    cudaGetSymbolAddress((void**)&p_h,   g_h);
    cudaGetSymbolAddress((void**)&p_deg, g_deg);

    static cudaStream_t s_csr = nullptr;
    static cudaEvent_t  ev_fork = nullptr, ev_join = nullptr;
    if (s_csr == nullptr) {
        cudaStreamCreateWithFlags(&s_csr, cudaStreamNonBlocking);
        cudaEventCreateWithFlags(&ev_fork, cudaEventDisableTiming);
        cudaEventCreateWithFlags(&ev_join, cudaEventDisableTiming);
        cudaFuncSetAttribute(mma_gemm_kernel<0>,
                             cudaFuncAttributeMaxDynamicSharedMemorySize, SM_BYTES);
        cudaFuncSetAttribute(mma_gemm_kernel<1>,
                             cudaFuncAttributeMaxDynamicSharedMemorySize, SM_BYTES);
    }

    const int gm = (Nn + 127) / 128;       // 391
    const int eb4 = (E / 4 + 255) / 256;
    const int agb = (Nn * 32 + 255) / 256;

    // ---- fork: CSR build on side stream, concurrent with layer-1 GEMM ----
    cudaEventRecord(ev_fork, 0);
    cudaStreamWaitEvent(s_csr, ev_fork, 0);

    detect_dtype_kernel<<<1, 32, 0, s_csr>>>((const int*)ei);
    cudaMemsetAsync(p_deg, 0, (size_t)Nn * sizeof(int), s_csr);
    hist_kernel<<<eb4, 256, 0, s_csr>>>(ei, E);
    scan_kernel<<<1, 1024, 0, s_csr>>>(Nn);
    scatter_kernel<<<eb4, 256, 0, s_csr>>>(ei, E);
    cudaEventRecord(ev_join, s_csr);

    // ---- layer 1 GEMMs (tensor via mma.sync) ----
    mma_gemm_kernel<0><<<dim3(gm, 1, 2), 256, SM_BYTES>>>(
        x, Wl1, bl1, p_xl, Wr1, br1, p_xr, Nn, 256, 64);

    cudaStreamWaitEvent(0, ev_join, 0);
    gat_aggregate_kernel<<<agb, 256>>>(p_xl, p_xr, att1, bias1, p_h, Nn);

    // ---- layer 2 ----
    mma_gemm_kernel<0><<<dim3(gm, 1, 2), 256, SM_BYTES>>>(
        p_h, Wl2, bl2, p_xl, Wr2, br2, p_xr, Nn, 64, 64);
    gat_aggregate_kernel<<<agb, 256>>>(p_xl, p_xr, att2, bias2, p_h, Nn);

    // ---- output head: sigmoid(h @ Wo + bo) -> d_out ----
    mma_gemm_kernel<1><<<dim3(gm, 4, 1), 256, SM_BYTES>>>(
        p_h, Wo, bo, (float*)d_out, Wo, bo, (float*)d_out, Nn, 64, 256);
}

// round 15
// speedup vs baseline: 1.2824x; 1.0142x over previous
#include <cuda_runtime.h>
#include <cstdint>

#define NMAX 50000
#define EMAX 1600000
#define HC   64
#define NEG_SLOPE 0.2f

// ---------------- device scratch (no allocation allowed) ----------------
__device__ float g_xl [NMAX * HC];
__device__ float g_xr [NMAX * HC];
__device__ float g_h  [NMAX * HC];
__device__ int   g_deg[NMAX];
__device__ int   g_off[NMAX + 1];
__device__ int   g_pos[NMAX];
__device__ int   g_csr_src[EMAX];
__device__ int   g_is64;

__device__ __forceinline__ float lrelu(float v) {
    return v > 0.f ? v : NEG_SLOPE * v;
}

__device__ __forceinline__ uint32_t tf32_round(float x) {
    uint32_t r;
    asm("cvt.rna.tf32.f32 %0, %1;" : "=r"(r) : "f"(x));
    return r;
}

// ---------------- dtype detect + degree zero (merged, 1 launch) -----------
__global__ void detect_zero_kernel(const int* __restrict__ w, int N) {
    int i = blockIdx.x * blockDim.x + threadIdx.x;
    if (i == 0) {
        int any = 0;
        for (int k = 0; k < 64; k++) any |= w[2 * k + 1];
        g_is64 = (any == 0) ? 1 : 0;
    }
    for (; i < N; i += gridDim.x * blockDim.x) g_deg[i] = 0;
}

__device__ __forceinline__ int load_idx(const void* ei, int i) {
    return g_is64 ? (int)((const long long*)ei)[i] : ((const int*)ei)[i];
}

// ---------------- CSR build (4 edges/thread) ------------------------------
__global__ void hist_kernel(const void* __restrict__ ei, int E) {
    int base = (blockIdx.x * blockDim.x + threadIdx.x) * 4;
    if (base >= E) return;
    int n = E - base; if (n > 4) n = 4;
    int d[4];
#pragma unroll
    for (int j = 0; j < 4; j++)
        if (j < n) d[j] = load_idx(ei, base + j + E);
#pragma unroll
    for (int j = 0; j < 4; j++)
        if (j < n) atomicAdd(&g_deg[d[j]], 1);
}

__global__ void __launch_bounds__(1024) scan_kernel(int N) {
    __shared__ int part[1024];
    int t = threadIdx.x;
    int chunk = (N + 1023) >> 10;
    int b = t * chunk; if (b > N) b = N;
    int e = b + chunk; if (e > N) e = N;
    int s = 0;
    for (int i = b; i < e; i++) s += g_deg[i];
    part[t] = s;
    __syncthreads();
    for (int d = 1; d < 1024; d <<= 1) {
        int v = (t >= d) ? part[t - d] : 0;
        __syncthreads();
        part[t] += v;
        __syncthreads();
    }
    int run = (t == 0) ? 0 : part[t - 1];
    for (int i = b; i < e; i++) {
        g_off[i] = run;
        g_pos[i] = run;
        run += g_deg[i];
    }
    if (e == N) g_off[N] = run;
}

__global__ void scatter_kernel(const void* __restrict__ ei, int E) {
    int base = (blockIdx.x * blockDim.x + threadIdx.x) * 4;
    if (base >= E) return;
    int n = E - base; if (n > 4) n = 4;
    int s[4], d[4];
#pragma unroll
    for (int j = 0; j < 4; j++)
        if (j < n) { s[j] = load_idx(ei, base + j); d[j] = load_idx(ei, base + j + E); }
    int slot[4];
#pragma unroll
    for (int j = 0; j < 4; j++)
        if (j < n) slot[j] = atomicAdd(&g_pos[d[j]], 1);
#pragma unroll
    for (int j = 0; j < 4; j++)
        if (j < n) g_csr_src[slot[j]] = s[j];
}

// ---------------- split-tf32 mma.sync GEMM (R12, unchanged) ---------------
#define ASTRIDE 36
#define BSTRIDE 72
#define SM_FLOATS (2 * 128 * ASTRIDE + 2 * 32 * BSTRIDE)   // 13824
#define SM_BYTES  (SM_FLOATS * 4)                          // 55296

__device__ __forceinline__ void mma8(float* c, const uint32_t* a, const uint32_t* b) {
    asm volatile(
        "mma.sync.aligned.m16n8k8.row.col.f32.tf32.tf32.f32 "
        "{%0,%1,%2,%3}, {%4,%5,%6,%7}, {%8,%9}, {%0,%1,%2,%3};"
        : "+f"(c[0]), "+f"(c[1]), "+f"(c[2]), "+f"(c[3])
        : "r"(a[0]), "r"(a[1]), "r"(a[2]), "r"(a[3]), "r"(b[0]), "r"(b[1]));
}

template<int ACT>  // 0 = none, 1 = sigmoid
__global__ void __launch_bounds__(256, 2) mma_gemm_kernel(
    const float* __restrict__ A,
    const float* __restrict__ W0, const float* __restrict__ b0, float* __restrict__ C0,
    const float* __restrict__ W1, const float* __restrict__ b1, float* __restrict__ C1,
    int M, int K, int NC)
{
    const float* W    = blockIdx.z ? W1 : W0;
    const float* bias = blockIdx.z ? b1 : b0;
    float*       C    = blockIdx.z ? C1 : C0;

    extern __shared__ float sm[];
    float* Ahi = sm;
    float* Alo = sm + 128 * ASTRIDE;
    float* Bhi = sm + 2 * 128 * ASTRIDE;
    float* Blo = Bhi + 32 * BSTRIDE;

    const int tid = threadIdx.x;
    const int wid = tid >> 5;
    const int lid = tid & 31;
    const int t   = lid & 3;
    const int g   = lid >> 2;
    const int wm  = wid & 3;
    const int wn  = wid >> 2;
    const int bm  = blockIdx.x * 128;
    const int bn  = blockIdx.y * 64;

    const int a_row = tid >> 3;
    const int a_c4  = (tid & 7) * 4;
    const int b_kr  = tid >> 4;
    const int b_cw  = (tid & 15) * 4;

    float acc[2][4][4];
#pragma unroll
    for (int i = 0; i < 2; i++)
#pragma unroll
        for (int j = 0; j < 4; j++)
#pragma unroll
            for (int q = 0; q < 4; q++) acc[i][j][q] = 0.f;

    float4 pa[4], pb[2];
#pragma unroll
    for (int it = 0; it < 4; it++) {
        int row = a_row + it * 32;
        pa[it] = make_float4(0.f, 0.f, 0.f, 0.f);
        if (bm + row < M)
            pa[it] = *(const float4*)(A + (size_t)(bm + row) * K + a_c4);
    }
#pragma unroll
    for (int it = 0; it < 2; it++) {
        int kr = b_kr + it * 16;
        pb[it] = *(const float4*)(W + (size_t)kr * NC + bn + b_cw);
    }

    for (int kk = 0; kk < K; kk += 32) {
#pragma unroll
        for (int it = 0; it < 4; it++) {
            int row = a_row + it * 32;
            float4 v = pa[it];
            float4 hf = make_float4(
                __uint_as_float(tf32_round(v.x)), __uint_as_float(tf32_round(v.y)),
                __uint_as_float(tf32_round(v.z)), __uint_as_float(tf32_round(v.w)));
            float4 lf = make_float4(
                __uint_as_float(tf32_round(v.x - hf.x)),
                __uint_as_float(tf32_round(v.y - hf.y)),
                __uint_as_float(tf32_round(v.z - hf.z)),
                __uint_as_float(tf32_round(v.w - hf.w)));
            *(float4*)(Ahi + row * ASTRIDE + a_c4) = hf;
            *(float4*)(Alo + row * ASTRIDE + a_c4) = lf;
        }
#pragma unroll
        for (int it = 0; it < 2; it++) {
            int kr = b_kr + it * 16;
            float4 v = pb[it];
            float4 hf = make_float4(
                __uint_as_float(tf32_round(v.x)), __uint_as_float(tf32_round(v.y)),
                __uint_as_float(tf32_round(v.z)), __uint_as_float(tf32_round(v.w)));
            float4 lf = make_float4(
                __uint_as_float(tf32_round(v.x - hf.x)),
                __uint_as_float(tf32_round(v.y - hf.y)),
                __uint_as_float(tf32_round(v.z - hf.z)),
                __uint_as_float(tf32_round(v.w - hf.w)));
            *(float4*)(Bhi + kr * BSTRIDE + b_cw) = hf;
            *(float4*)(Blo + kr * BSTRIDE + b_cw) = lf;
        }
        __syncthreads();

        if (kk + 32 < K) {
#pragma unroll
            for (int it = 0; it < 4; it++) {
                int row = a_row + it * 32;
                pa[it] = make_float4(0.f, 0.f, 0.f, 0.f);
                if (bm + row < M)
                    pa[it] = *(const float4*)(A + (size_t)(bm + row) * K + kk + 32 + a_c4);
            }
#pragma unroll
            for (int it = 0; it < 2; it++) {
                int kr = b_kr + it * 16;
                pb[it] = *(const float4*)(W + (size_t)(kk + 32 + kr) * NC + bn + b_cw);
            }
        }

#pragma unroll
        for (int q = 0; q < 4; q++) {
            const int kq = q * 8;
            uint32_t ahi[2][4], alo[2][4];
#pragma unroll
            for (int i = 0; i < 2; i++) {
                int mb = wm * 32 + i * 16;
                const uint32_t* ph = (const uint32_t*)Ahi;
                const uint32_t* pl = (const uint32_t*)Alo;
                int o00 = (mb + g)     * ASTRIDE + kq + t;
                int o10 = (mb + g + 8) * ASTRIDE + kq + t;
                ahi[i][0] = ph[o00];     ahi[i][1] = ph[o10];
                ahi[i][2] = ph[o00 + 4]; ahi[i][3] = ph[o10 + 4];
                alo[i][0] = pl[o00];     alo[i][1] = pl[o10];
                alo[i][2] = pl[o00 + 4]; alo[i][3] = pl[o10 + 4];
            }
            uint32_t bh[4][2], bl[4][2];
#pragma unroll
            for (int j = 0; j < 4; j++) {
                int nb = wn * 32 + j * 8;
                const uint32_t* ph = (const uint32_t*)Bhi;
                const uint32_t* pl = (const uint32_t*)Blo;
                int o0 = (kq + t)     * BSTRIDE + nb + g;
                int o1 = (kq + t + 4) * BSTRIDE + nb + g;
                bh[j][0] = ph[o0]; bh[j][1] = ph[o1];
                bl[j][0] = pl[o0]; bl[j][1] = pl[o1];
            }
#pragma unroll
            for (int i = 0; i < 2; i++)
#pragma unroll
                for (int j = 0; j < 4; j++) {
                    mma8(acc[i][j], ahi[i], bh[j]);
                    mma8(acc[i][j], ahi[i], bl[j]);
                    mma8(acc[i][j], alo[i], bh[j]);
                }
        }
        __syncthreads();
    }

#pragma unroll
    for (int i = 0; i < 2; i++) {
        int r0 = bm + wm * 32 + i * 16 + g;
#pragma unroll
        for (int j = 0; j < 4; j++) {
            int col = bn + wn * 32 + j * 8 + 2 * t;
            float bz0 = bias[col], bz1 = bias[col + 1];
            float v0 = acc[i][j][0] + bz0;
            float v1 = acc[i][j][1] + bz1;
            float v2 = acc[i][j][2] + bz0;
            float v3 = acc[i][j][3] + bz1;
            if (ACT == 1) {
                v0 = 1.f / (1.f + __expf(-v0));
                v1 = 1.f / (1.f + __expf(-v1));
                v2 = 1.f / (1.f + __expf(-v2));
                v3 = 1.f / (1.f + __expf(-v3));
            }
            if (r0 < M)
                *(float2*)(C + (size_t)r0 * NC + col) = make_float2(v0, v1);
            if (r0 + 8 < M)
                *(float2*)(C + (size_t)(r0 + 8) * NC + col) = make_float2(v2, v3);
        }
    }
}

// ---------------- fused per-node GATv2 aggregation (deep-MLP) -------------
// Warp per dst node. Lanes 0-15 edge j, lanes 16-31 edge j+1.
// q = lid&15 owns channels 4q..4q+3. Main loop: 16 edges per iter with
// 8 LDG.128 batched in flight (4KB/warp) to cover L2 latency.
__global__ void __launch_bounds__(256) gat_aggregate_kernel(
    const float* __restrict__ xl, const float* __restrict__ xr,
    const float* __restrict__ att, const float* __restrict__ bias,
    float* __restrict__ out, int N)
{
    const int warp = (blockIdx.x * blockDim.x + threadIdx.x) >> 5;
    const int lid  = threadIdx.x & 31;
    if (warp >= N) return;
    const int d  = warp;
    const int eh = lid >> 4;      // edge half: 0 or 1
    const int q  = lid & 15;      // channel quad

    const float4 a4  = *(const float4*)(att + q * 4);
    const float4 xr4 = *(const float4*)(xr + (size_t)d * 64 + q * 4);

    const int beg = g_off[d];
    const int end = g_off[d + 1];

    float4 acc = make_float4(0.f, 0.f, 0.f, 0.f);
    float  den = 0.f;

    for (int i = beg; i < end; ) {
        int cnt = end - i;
        if (cnt > 32) cnt = 32;
        int my_src = (lid < cnt) ? g_csr_src[i + lid] : 0;

        int j = 0;
        // 16 edges per iter: 8 batched loads in flight
        for (; j + 16 <= cnt; j += 16) {
            int s[8];
            float4 v[8];
#pragma unroll
            for (int u = 0; u < 8; u++)
                s[u] = __shfl_sync(0xffffffffu, my_src, j + 2 * u + eh);
#pragma unroll
            for (int u = 0; u < 8; u++)
                v[u] = *(const float4*)(xl + (size_t)s[u] * 64 + q * 4);
#pragma unroll
            for (int u = 0; u < 8; u++) {
                float p = a4.x * lrelu(v[u].x + xr4.x)
                        + a4.y * lrelu(v[u].y + xr4.y)
                        + a4.z * lrelu(v[u].z + xr4.z)
                        + a4.w * lrelu(v[u].w + xr4.w);
                p += __shfl_xor_sync(0xffffffffu, p, 1);
                p += __shfl_xor_sync(0xffffffffu, p, 2);
                float ex = __expf(p);
                den   += ex;
                acc.x += ex * v[u].x;
                acc.y += ex * v[u].y;
                acc.z += ex * v[u].z;
                acc.w += ex * v[u].w;
            }
        }
        // 8-edge path
        for (; j + 8 <= cnt; j += 8) {
            int s[4];
            float4 v[4];
#pragma unroll
            for (int u = 0; u < 4; u++)
                s[u] = __shfl_sync(0xffffffffu, my_src, j + 2 * u + eh);
#pragma unroll
            for (int u = 0; u < 4; u++)
                v[u] = *(const float4*)(xl + (size_t)s[u] * 64 + q * 4);
#pragma unroll
            for (int u = 0; u < 4; u++) {
                float p = a4.x * lrelu(v[u].x + xr4.x)
                        + a4.y * lrelu(v[u].y + xr4.y)
                        + a4.z * lrelu(v[u].z + xr4.z)
                        + a4.w * lrelu(v[u].w + xr4.w);
                p += __shfl_xor_sync(0xffffffffu, p, 1);
                p += __shfl_xor_sync(0xffffffffu, p, 2);
                float ex = __expf(p);
                den   += ex;
                acc.x += ex * v[u].x;
                acc.y += ex * v[u].y;
                acc.z += ex * v[u].z;
                acc.w += ex * v[u].w;
            }
        }
        // remainder: 2 edges at a time, tail-guarded
        for (; j < cnt; j += 2) {
            int idx   = j + eh;
            bool val  = idx < cnt;
            int s     = __shfl_sync(0xffffffffu, my_src, val ? idx : 0);
            float4 v  = make_float4(0.f, 0.f, 0.f, 0.f);
            if (val) v = *(const float4*)(xl + (size_t)s * 64 + q * 4);
            float p = a4.x * lrelu(v.x + xr4.x)
                    + a4.y * lrelu(v.y + xr4.y)
                    + a4.z * lrelu(v.z + xr4.z)
                    + a4.w * lrelu(v.w + xr4.w);
            p += __shfl_xor_sync(0xffffffffu, p, 1);
            p += __shfl_xor_sync(0xffffffffu, p, 2);
            float ex = val ? __expf(p) : 0.f;
            den   += ex;
            acc.x += ex * v.x;
            acc.y += ex * v.y;
            acc.z += ex * v.z;
            acc.w += ex * v.w;
        }
        i += cnt;
    }

    // combine the two edge-halves (xor 16)
    acc.x += __shfl_xor_sync(0xffffffffu, acc.x, 16);
    acc.y += __shfl_xor_sync(0xffffffffu, acc.y, 16);
    acc.z += __shfl_xor_sync(0xffffffffu, acc.z, 16);
    acc.w += __shfl_xor_sync(0xffffffffu, acc.w, 16);
    den   += __shfl_xor_sync(0xffffffffu, den,   16);

    if (eh == 0) {
        float inv = (den > 0.f) ? (1.f / den) : 0.f;
        float4 b4 = *(const float4*)(bias + q * 4);
        float4 o;
        o.x = fmaxf(acc.x * inv + b4.x, 0.f);
        o.y = fmaxf(acc.y * inv + b4.y, 0.f);
        o.z = fmaxf(acc.z * inv + b4.z, 0.f);
        o.w = fmaxf(acc.w * inv + b4.w, 0.f);
        *(float4*)(out + (size_t)d * 64 + q * 4) = o;
    }
}

// ---------------- launch --------------------------------------------------
extern "C" void kernel_launch(void* const* d_in, const int* in_sizes, int n_in,
                              void* d_out, int out_size)
{
    const float* x    = (const float*)d_in[0];
    const void*  ei   = d_in[1];
    const float* Wl1  = (const float*)d_in[2];
    const float* bl1  = (const float*)d_in[3];
    const float* Wr1  = (const float*)d_in[4];
    const float* br1  = (const float*)d_in[5];
    const float* att1 = (const float*)d_in[6];
    const float* bias1= (const float*)d_in[7];
    const float* Wl2  = (const float*)d_in[8];
    const float* bl2  = (const float*)d_in[9];
    const float* Wr2  = (const float*)d_in[10];
    const float* br2  = (const float*)d_in[11];
    const float* att2 = (const float*)d_in[12];
    const float* bias2= (const float*)d_in[13];
    const float* Wo   = (const float*)d_in[14];
    const float* bo   = (const float*)d_in[15];

    const int Nn = in_sizes[0] / 256;      // 50000
    const int E  = in_sizes[1] / 2;        // 1600000

    float *p_xl, *p_xr, *p_h;
    cudaGetSymbolAddress((void**)&p_xl,  g_xl);
    cudaGetSymbolAddress((void**)&p_xr,  g_xr);
    cudaGetSymbolAddress((void**)&p_h,   g_h);

    static cudaStream_t s_csr = nullptr;
    static cudaEvent_t  ev_fork = nullptr, ev_join = nullptr;
    if (s_csr == nullptr) {
        cudaStreamCreateWithFlags(&s_csr, cudaStreamNonBlocking);
        cudaEventCreateWithFlags(&ev_fork, cudaEventDisableTiming);
        cudaEventCreateWithFlags(&ev_join, cudaEventDisableTiming);
        cudaFuncSetAttribute(mma_gemm_kernel<0>,
                             cudaFuncAttributeMaxDynamicSharedMemorySize, SM_BYTES);
        cudaFuncSetAttribute(mma_gemm_kernel<1>,
                             cudaFuncAttributeMaxDynamicSharedMemorySize, SM_BYTES);
    }

    const int gm = (Nn + 127) / 128;       // 391
    const int eb4 = (E / 4 + 255) / 256;
    const int agb = (Nn * 32 + 255) / 256;

    // ---- fork: CSR build on side stream, concurrent with layer-1 GEMM ----
    cudaEventRecord(ev_fork, 0);
    cudaStreamWaitEvent(s_csr, ev_fork, 0);

    detect_zero_kernel<<<64, 1024, 0, s_csr>>>((const int*)ei, Nn);
    hist_kernel<<<eb4, 256, 0, s_csr>>>(ei, E);
    scan_kernel<<<1, 1024, 0, s_csr>>>(Nn);
    scatter_kernel<<<eb4, 256, 0, s_csr>>>(ei, E);
    cudaEventRecord(ev_join, s_csr);

    // ---- layer 1 GEMMs (tensor via mma.sync) ----
    mma_gemm_kernel<0><<<dim3(gm, 1, 2), 256, SM_BYTES>>>(
        x, Wl1, bl1, p_xl, Wr1, br1, p_xr, Nn, 256, 64);

    cudaStreamWaitEvent(0, ev_join, 0);
    gat_aggregate_kernel<<<agb, 256>>>(p_xl, p_xr, att1, bias1, p_h, Nn);

    // ---- layer 2 ----
    mma_gemm_kernel<0><<<dim3(gm, 1, 2), 256, SM_BYTES>>>(
        p_h, Wl2, bl2, p_xl, Wr2, br2, p_xr, Nn, 64, 64);
    gat_aggregate_kernel<<<agb, 256>>>(p_xl, p_xr, att2, bias2, p_h, Nn);

    // ---- output head: sigmoid(h @ Wo + bo) -> d_out ----
    mma_gemm_kernel<1><<<dim3(gm, 4, 1), 256, SM_BYTES>>>(
        p_h, Wo, bo, (float*)d_out, Wo, bo, (float*)d_out, Nn, 64, 256);
}